// round 1
// baseline (speedup 1.0000x reference)
#include <cuda_runtime.h>
#include <math.h>

// ---------------- Problem constants ----------------
#define D_    768
#define H_    12
#define HD_   64
#define S_    197
#define L_    196
#define NB    16          // batch per image set
#define B2    32          // both image sets
#define FF_   3072
#define OUT_  512
#define QKV3  2304
#define IMG_  224
#define GRID_ 14
#define PCH_  16

// ---------------- Scratch (device globals; no allocation allowed) ----------------
__device__ float g_x12[B2 * S_ * D_];      // residual stream (x | x2)
__device__ float g_xln[B2 * S_ * D_];      // LN output
__device__ float g_qkv[B2 * S_ * QKV3];    // qkv
__device__ float g_att[B2 * S_ * D_];      // attention out (also conv_out temp)
__device__ float g_ffh[B2 * S_ * FF_];     // MLP hidden
__device__ float g_im2col[B2 * L_ * D_];   // patch im2col
__device__ float g_clsb[NB * L_];          // cls-row attention bias

// ======================================================================
// GEMM: C[M,N] = act( A[M,K] @ B[N,K]^T + bias[N] ) + resid[M,N]
// 128x128 tile, BK=8, 256 threads, 8x8 microtile (z-ordered), float4 smem.
// ======================================================================
__global__ __launch_bounds__(256) void gemm_kernel(
    const float* __restrict__ A, const float* __restrict__ B,
    const float* __restrict__ bias, const float* __restrict__ resid,
    float* __restrict__ C, int M, int N, int K, int act)
{
    __shared__ float As[8][132];
    __shared__ float Bs[8][132];

    const int bm = blockIdx.y * 128;
    const int bn = blockIdx.x * 128;
    const int tid = threadIdx.x;
    const int tx = tid & 15;       // 0..15
    const int ty = tid >> 4;       // 0..15

    const int lrow = tid >> 1;            // 0..127
    const int lcol = (tid & 1) * 4;       // 0 or 4

    float acc[8][8];
    #pragma unroll
    for (int i = 0; i < 8; i++)
        #pragma unroll
        for (int j = 0; j < 8; j++) acc[i][j] = 0.f;

    const bool avalid = (bm + lrow) < M;
    const float* Aptr = A + (size_t)(bm + lrow) * K + lcol;
    const float* Bptr = B + (size_t)(bn + lrow) * K + lcol;

    for (int k0 = 0; k0 < K; k0 += 8) {
        float4 av = avalid ? *(const float4*)(Aptr + k0) : make_float4(0.f, 0.f, 0.f, 0.f);
        float4 bv = *(const float4*)(Bptr + k0);
        As[lcol + 0][lrow] = av.x; As[lcol + 1][lrow] = av.y;
        As[lcol + 2][lrow] = av.z; As[lcol + 3][lrow] = av.w;
        Bs[lcol + 0][lrow] = bv.x; Bs[lcol + 1][lrow] = bv.y;
        Bs[lcol + 2][lrow] = bv.z; Bs[lcol + 3][lrow] = bv.w;
        __syncthreads();

        #pragma unroll
        for (int kk = 0; kk < 8; kk++) {
            float a[8], b[8];
            *(float4*)&a[0] = *(const float4*)&As[kk][ty * 4];
            *(float4*)&a[4] = *(const float4*)&As[kk][64 + ty * 4];
            *(float4*)&b[0] = *(const float4*)&Bs[kk][tx * 4];
            *(float4*)&b[4] = *(const float4*)&Bs[kk][64 + tx * 4];
            #pragma unroll
            for (int i = 0; i < 8; i++)
                #pragma unroll
                for (int j = 0; j < 8; j++)
                    acc[i][j] += a[i] * b[j];
        }
        __syncthreads();
    }

    #pragma unroll
    for (int i = 0; i < 8; i++) {
        int gm = bm + ((i < 4) ? (ty * 4 + i) : (64 + ty * 4 + i - 4));
        if (gm >= M) continue;
        #pragma unroll
        for (int j = 0; j < 8; j++) {
            int gn = bn + ((j < 4) ? (tx * 4 + j) : (64 + tx * 4 + j - 4));
            float v = acc[i][j];
            if (bias)  v += bias[gn];
            if (act)   v = v / (1.f + expf(-1.702f * v));   // GELU(sigmoid approx)
            if (resid) v += resid[(size_t)gm * N + gn];
            C[(size_t)gm * N + gn] = v;
        }
    }
}

// ======================================================================
// LayerNorm: one block (256 thr) per row of 768.
// ======================================================================
__global__ __launch_bounds__(256) void ln_kernel(
    const float* __restrict__ x, long in_stride,
    float* __restrict__ y, long out_stride,
    const float* __restrict__ g, const float* __restrict__ b, int rows)
{
    int r = blockIdx.x;
    if (r >= rows) return;
    const float* xr = x + (size_t)r * in_stride;
    float* yr = y + (size_t)r * out_stride;
    int t = threadIdx.x;

    float v0 = xr[t], v1 = xr[t + 256], v2 = xr[t + 512];

    __shared__ float red[8];
    __shared__ float bc;

    // mean
    float s = v0 + v1 + v2;
    #pragma unroll
    for (int o = 16; o > 0; o >>= 1) s += __shfl_xor_sync(0xffffffffu, s, o);
    if ((t & 31) == 0) red[t >> 5] = s;
    __syncthreads();
    if (t == 0) { float tot = 0.f; for (int i = 0; i < 8; i++) tot += red[i]; bc = tot; }
    __syncthreads();
    float mu = bc * (1.f / 768.f);

    float d0 = v0 - mu, d1 = v1 - mu, d2 = v2 - mu;
    float ss = d0 * d0 + d1 * d1 + d2 * d2;
    #pragma unroll
    for (int o = 16; o > 0; o >>= 1) ss += __shfl_xor_sync(0xffffffffu, ss, o);
    __syncthreads();            // protect red[] reuse
    if ((t & 31) == 0) red[t >> 5] = ss;
    __syncthreads();
    if (t == 0) { float tot = 0.f; for (int i = 0; i < 8; i++) tot += red[i]; bc = tot; }
    __syncthreads();
    float rs = rsqrtf(bc * (1.f / 768.f) + 1e-5f);

    yr[t]       = d0 * rs * g[t]       + b[t];
    yr[t + 256] = d1 * rs * g[t + 256] + b[t + 256];
    yr[t + 512] = d2 * rs * g[t + 512] + b[t + 512];
}

// ======================================================================
// Fused attention: one block per (head, batch). K,V in smem (stride-68
// padded, conflict-free float4). 8 warps; each warp owns queries w, w+8, ...
// ======================================================================
#define KVS 68
__global__ __launch_bounds__(256) void attn_kernel(
    const float* __restrict__ qkv, const float* __restrict__ clsbias,
    float* __restrict__ out)
{
    extern __shared__ float sm[];
    float* Ks = sm;                       // 197*68
    float* Vs = sm + S_ * KVS;            // 197*68
    float* Ps = Vs + S_ * KVS;            // 8*200

    const int h = blockIdx.x, b = blockIdx.y;
    const int tid = threadIdx.x;
    const int w = tid >> 5, lane = tid & 31;
    const size_t base = (size_t)b * S_ * QKV3;

    for (int i = tid; i < S_ * HD_; i += 256) {
        int s_ = i >> 6, hd = i & 63;
        size_t off = base + (size_t)s_ * QKV3 + h * HD_ + hd;
        Ks[s_ * KVS + hd] = qkv[off + D_];
        Vs[s_ * KVS + hd] = qkv[off + 2 * D_];
    }
    __syncthreads();

    for (int q = w; q < S_; q += 8) {
        const float4* qp = (const float4*)(qkv + base + (size_t)q * QKV3 + h * HD_);
        float4 qr[16];
        #pragma unroll
        for (int i = 0; i < 16; i++) qr[i] = qp[i];

        float sc[7];
        #pragma unroll
        for (int t = 0; t < 7; t++) {
            int k = lane + 32 * t;
            float sv = -1e30f;
            if (k < S_) {
                const float4* kp = (const float4*)(Ks + k * KVS);
                float a = 0.f;
                #pragma unroll
                for (int i = 0; i < 16; i++) {
                    float4 kk = kp[i];
                    a += qr[i].x * kk.x + qr[i].y * kk.y + qr[i].z * kk.z + qr[i].w * kk.w;
                }
                sv = a * 0.125f;
                if (clsbias && q == 0 && k >= 1) sv += clsbias[b * L_ + (k - 1)];
            }
            sc[t] = sv;
        }
        // softmax over k (warp-wide)
        float m = sc[0];
        #pragma unroll
        for (int t = 1; t < 7; t++) m = fmaxf(m, sc[t]);
        #pragma unroll
        for (int o = 16; o > 0; o >>= 1) m = fmaxf(m, __shfl_xor_sync(0xffffffffu, m, o));
        float se = 0.f;
        #pragma unroll
        for (int t = 0; t < 7; t++) {
            float e = (sc[t] > -1e29f) ? expf(sc[t] - m) : 0.f;
            sc[t] = e; se += e;
        }
        #pragma unroll
        for (int o = 16; o > 0; o >>= 1) se += __shfl_xor_sync(0xffffffffu, se, o);
        float inv = 1.f / se;
        #pragma unroll
        for (int t = 0; t < 7; t++) {
            int k = lane + 32 * t;
            if (k < S_) Ps[w * 200 + k] = sc[t] * inv;
        }
        __syncwarp();

        float o0 = 0.f, o1 = 0.f;
        for (int k = 0; k < S_; k++) {
            float p = Ps[w * 200 + k];
            o0 += p * Vs[k * KVS + lane];
            o1 += p * Vs[k * KVS + 32 + lane];
        }
        size_t orow = ((size_t)b * S_ + q) * D_ + h * HD_;
        out[orow + lane] = o0;
        out[orow + 32 + lane] = o1;
        __syncwarp();
    }
}

// ======================================================================
// Patch embed helpers
// ======================================================================
__global__ void im2col_kernel(const float* __restrict__ masked,
                              const float* __restrict__ prompted,
                              float* __restrict__ col)
{
    int idx = blockIdx.x * 256 + threadIdx.x;
    const int total = B2 * L_ * D_;
    if (idx >= total) return;
    int k = idx % D_;
    int m = idx / D_;
    int b = m / L_, l = m % L_;
    int gy = l / GRID_, gx = l % GRID_;
    int c = k >> 8, rem = k & 255;
    int py = rem >> 4, px = rem & 15;
    const float* src = (b < NB) ? (masked + (size_t)b * 3 * IMG_ * IMG_)
                                : (prompted + (size_t)(b - NB) * 3 * IMG_ * IMG_);
    col[idx] = src[((size_t)c * IMG_ + gy * PCH_ + py) * IMG_ + gx * PCH_ + px];
}

__global__ void embed_kernel(const float* __restrict__ conv_out,
                             const float* __restrict__ cls_emb,
                             const float* __restrict__ pos,
                             float* __restrict__ x)
{
    int idx = blockIdx.x * 256 + threadIdx.x;
    const int total = B2 * S_ * D_;
    if (idx >= total) return;
    int d = idx % D_;
    int bs = idx / D_;
    int s = bs % S_, b = bs / S_;
    float v = (s == 0) ? cls_emb[d] : conv_out[((size_t)b * L_ + (s - 1)) * D_ + d];
    x[idx] = v + pos[s * D_ + d];
}

__global__ void clsbias_kernel(const float* __restrict__ pm, float* __restrict__ cb)
{
    int i = blockIdx.x * 256 + threadIdx.x;
    if (i < NB * L_) cb[i] = (pm[i] != 0.f) ? 0.f : -1e30f;
}

// xa: x[:16] = 2 * (x2 with tokens masked) + x    (in place on x region)
__global__ void mask_combine_kernel(float* __restrict__ x, const float* __restrict__ x2,
                                    const float* __restrict__ pm)
{
    int idx = blockIdx.x * 256 + threadIdx.x;
    const int total = NB * S_ * D_;
    if (idx >= total) return;
    int bs = idx / D_;
    int s = bs % S_, b = bs / S_;
    float mf = (s == 0) ? 1.f : pm[b * L_ + (s - 1)];
    x[idx] = 2.f * x2[idx] * mf + x[idx];
}

// final: out[16,512] = cls_ln[16,768] @ proj[768,512]
__global__ void proj_out_kernel(const float* __restrict__ cls,
                                const float* __restrict__ proj,
                                float* __restrict__ out)
{
    int n = blockIdx.x * 256 + threadIdx.x;
    int m = blockIdx.y;
    if (n >= OUT_) return;
    float s = 0.f;
    #pragma unroll 4
    for (int k = 0; k < D_; k++) s += cls[m * D_ + k] * proj[(size_t)k * OUT_ + n];
    out[m * OUT_ + n] = s;
}

// ======================================================================
// Host orchestration
// ======================================================================
static float* symaddr(const void* s) {
    void* p = nullptr;
    cudaGetSymbolAddress(&p, s);
    return (float*)p;
}

static void run_gemm(const float* A, const float* B, const float* bias,
                     const float* resid, float* C, int M, int N, int K, int act)
{
    dim3 grid(N / 128, (M + 127) / 128);
    gemm_kernel<<<grid, 256>>>(A, B, bias, resid, C, M, N, K, act);
}

struct Ctx {
    float *x12, *xln, *qkv, *att, *ffh, *col, *clsb;
    const float *Wqkv, *bqkv, *Wo, *bo, *ln1g, *ln1b, *ln2g, *ln2b, *Wfc, *bfc, *Wp, *bp;
    int attn_smem;
};

static void run_block(const Ctx& c, float* x, int Bn, int layer, const float* bias)
{
    const int M = Bn * S_;
    ln_kernel<<<M, 256>>>(x, D_, c.xln, D_, c.ln1g + layer * D_, c.ln1b + layer * D_, M);
    run_gemm(c.xln, c.Wqkv + (size_t)layer * QKV3 * D_, c.bqkv + layer * QKV3,
             nullptr, c.qkv, M, QKV3, D_, 0);
    attn_kernel<<<dim3(H_, Bn), 256, c.attn_smem>>>(c.qkv, bias, c.att);
    run_gemm(c.att, c.Wo + (size_t)layer * D_ * D_, c.bo + layer * D_,
             x, x, M, D_, D_, 0);
    ln_kernel<<<M, 256>>>(x, D_, c.xln, D_, c.ln2g + layer * D_, c.ln2b + layer * D_, M);
    run_gemm(c.xln, c.Wfc + (size_t)layer * FF_ * D_, c.bfc + layer * FF_,
             nullptr, c.ffh, M, FF_, D_, 1);
    run_gemm(c.ffh, c.Wp + (size_t)layer * D_ * FF_, c.bp + layer * D_,
             x, x, M, D_, FF_, 0);
}

extern "C" void kernel_launch(void* const* d_in, const int* in_sizes, int n_in,
                              void* d_out, int out_size)
{
    const float* masked   = (const float*)d_in[0];
    const float* prompted = (const float*)d_in[1];
    const float* pred     = (const float*)d_in[2];
    const float* conv_w   = (const float*)d_in[3];
    const float* cls_emb  = (const float*)d_in[4];
    const float* pos_emb  = (const float*)d_in[5];
    const float* lnpre_g  = (const float*)d_in[6];
    const float* lnpre_b  = (const float*)d_in[7];

    Ctx c;
    c.Wqkv = (const float*)d_in[8];   c.bqkv = (const float*)d_in[9];
    c.Wo   = (const float*)d_in[10];  c.bo   = (const float*)d_in[11];
    c.ln1g = (const float*)d_in[12];  c.ln1b = (const float*)d_in[13];
    c.ln2g = (const float*)d_in[14];  c.ln2b = (const float*)d_in[15];
    c.Wfc  = (const float*)d_in[16];  c.bfc  = (const float*)d_in[17];
    c.Wp   = (const float*)d_in[18];  c.bp   = (const float*)d_in[19];
    const float* lnpost_g = (const float*)d_in[20];
    const float* lnpost_b = (const float*)d_in[21];
    const float* proj     = (const float*)d_in[22];
    float* out = (float*)d_out;

    c.x12  = symaddr(g_x12);
    c.xln  = symaddr(g_xln);
    c.qkv  = symaddr(g_qkv);
    c.att  = symaddr(g_att);
    c.ffh  = symaddr(g_ffh);
    c.col  = symaddr(g_im2col);
    c.clsb = symaddr(g_clsb);

    c.attn_smem = (2 * S_ * KVS + 8 * 200) * (int)sizeof(float);   // 113,568 B
    cudaFuncSetAttribute(attn_kernel, cudaFuncAttributeMaxDynamicSharedMemorySize,
                         c.attn_smem);

    // ---- patch embed (im2col GEMM) ----
    {
        const int total = B2 * L_ * D_;
        im2col_kernel<<<(total + 255) / 256, 256>>>(masked, prompted, c.col);
        // conv_w is (768, 3*16*16) contiguous → exactly (N,K) for our GEMM
        run_gemm(c.col, conv_w, nullptr, nullptr, c.att, B2 * L_, D_, D_, 0);
        const int tot2 = B2 * S_ * D_;
        embed_kernel<<<(tot2 + 255) / 256, 256>>>(c.att, cls_emb, pos_emb, c.x12);
        ln_kernel<<<B2 * S_, 256>>>(c.x12, D_, c.x12, D_, lnpre_g, lnpre_b, B2 * S_);
    }

    clsbias_kernel<<<(NB * L_ + 255) / 256, 256>>>(pred, c.clsb);

    // ---- 10 standard blocks on the concatenated batch ----
    for (int i = 0; i < 10; i++)
        run_block(c, c.x12, B2, i, nullptr);

    // ---- masking phase: layers 10 and 11 ----
    float* x  = c.x12;
    float* x2 = c.x12 + (size_t)NB * S_ * D_;
    const int layers2[2] = {10, 11};
    for (int t = 0; t < 2; t++) {
        int i = layers2[t];
        const int tot = NB * S_ * D_;
        mask_combine_kernel<<<(tot + 255) / 256, 256>>>(x, x2, pred);
        run_block(c, x, NB, i, nullptr);
        run_block(c, x2, NB, i, c.clsb);
    }

    // ---- head: LN_post on cls token, then @ proj ----
    ln_kernel<<<NB, 256>>>(x, (long)S_ * D_, c.xln, D_, lnpost_g, lnpost_b, NB);
    proj_out_kernel<<<dim3((OUT_ + 255) / 256, NB), 256>>>(c.xln, proj, out);

    (void)in_sizes; (void)n_in; (void)out_size;
}